// round 2
// baseline (speedup 1.0000x reference)
#include <cuda_runtime.h>
#include <cstdint>

// ---------------------------------------------------------------------------
// Problem constants
// ---------------------------------------------------------------------------
#define BATCH 8
#define CDIM  256
#define NPOS  1024          // H*W = 32*32
#define NH    16
#define KDIM  16            // key dim per head
#define DV    64            // value dim per head
#define DH    (NH*DV)       // 1024
#define HID   1024

// ---------------------------------------------------------------------------
// Scratch (device global; no allocations allowed)
// Offsets in floats.
// ---------------------------------------------------------------------------
#define OFF_Y   0u                       // [8,256,1024]   BN1 out
#define OFF_Q   (OFF_Y  + 2097152u)      // [8,256,1024]
#define OFF_K   (OFF_Q  + 2097152u)      // [8,256,1024]
#define OFF_V   (OFF_K  + 2097152u)      // [8,1024,1024]
#define OFF_O   (OFF_V  + 8388608u)      // [8,1024,1024]
#define OFF_X2  (OFF_O  + 8388608u)      // [8,256,1024]   after attn residual
#define OFF_Y2  (OFF_X2 + 2097152u)      // [8,256,1024]   BN2 out
#define OFF_H   (OFF_Y2 + 2097152u)      // [8,1024,1024]  MLP hidden
#define SCRATCH_FLOATS (OFF_H + 8388608u)

__device__ float g_buf[SCRATCH_FLOATS];

// ---------------------------------------------------------------------------
// Fused BatchNorm1d (train-mode stats over (B, N), biased var) + affine.
// grid = C channels, block = 256 threads.
// ---------------------------------------------------------------------------
__global__ void __launch_bounds__(256) bn_kernel(
    const float* __restrict__ x, float* __restrict__ y,
    const float* __restrict__ gamma, const float* __restrict__ beta)
{
    const int c   = blockIdx.x;
    const int tid = threadIdx.x;
    __shared__ float sh[512];

    float s = 0.f, s2 = 0.f;
    for (int idx = tid; idx < BATCH * NPOS; idx += 256) {
        int bb = idx >> 10, n = idx & 1023;
        float v = x[((size_t)bb * CDIM + c) * NPOS + n];
        s += v; s2 += v * v;
    }
    sh[tid] = s; sh[256 + tid] = s2;
    __syncthreads();
    for (int off = 128; off; off >>= 1) {
        if (tid < off) { sh[tid] += sh[tid + off]; sh[256 + tid] += sh[256 + tid + off]; }
        __syncthreads();
    }
    const float inv_n = 1.0f / (float)(BATCH * NPOS);
    float mean = sh[0] * inv_n;
    float var  = sh[256] * inv_n - mean * mean;
    float scale = gamma[c] * rsqrtf(var + 1e-5f);
    float shift = beta[c] - mean * scale;

    for (int idx = tid; idx < BATCH * NPOS; idx += 256) {
        int bb = idx >> 10, n = idx & 1023;
        size_t off2 = ((size_t)bb * CDIM + c) * NPOS + n;
        y[off2] = x[off2] * scale + shift;
    }
}

// ---------------------------------------------------------------------------
// Batched SGEMM: out[z][m][n] = act(sum_k W[m][k]*Y[z][k][n] + bias[m]) (+ R[z][m][n])
// Tiles 64x64x16, 256 threads, 4x4 per-thread micro-tile, float4 smem reads.
// grid = (NN/64, M/64, BATCH)
// ---------------------------------------------------------------------------
template<int RELU6, int ADDRES>
__global__ void __launch_bounds__(256) gemm_kernel(
    const float* __restrict__ W, const float* __restrict__ Y,
    const float* __restrict__ bias, const float* __restrict__ R,
    float* __restrict__ out, int M, int K, int NN)
{
    __shared__ float Wst[16][68];   // [k][m_local]
    __shared__ float Ys [16][68];   // [k][n_local]

    const int tid = threadIdx.x;
    const int tx  = tid & 15;       // n group
    const int ty  = tid >> 4;       // m group
    const int n0  = blockIdx.x * 64;
    const int m0  = blockIdx.y * 64;
    const size_t zY = (size_t)blockIdx.z * K * NN;
    const size_t zO = (size_t)blockIdx.z * M * NN;
    const float* Yb = Y + zY;

    float4 acc0 = {0,0,0,0}, acc1 = {0,0,0,0}, acc2 = {0,0,0,0}, acc3 = {0,0,0,0};

    for (int k0 = 0; k0 < K; k0 += 16) {
        // W tile: 64 m x 16 k
        {
            int j = tid & 15, ib = tid >> 4;
            #pragma unroll
            for (int p = 0; p < 4; ++p) {
                int i = ib + p * 16;
                Wst[j][i] = W[(size_t)(m0 + i) * K + (k0 + j)];
            }
            int jj = tid >> 6, ii = tid & 63;
            #pragma unroll
            for (int p = 0; p < 4; ++p) {
                int j2 = jj + p * 4;
                Ys[j2][ii] = Yb[(size_t)(k0 + j2) * NN + (n0 + ii)];
            }
        }
        __syncthreads();
        #pragma unroll
        for (int kk = 0; kk < 16; ++kk) {
            float4 a = *(const float4*)&Wst[kk][ty * 4];
            float4 b = *(const float4*)&Ys [kk][tx * 4];
            acc0.x += a.x*b.x; acc0.y += a.x*b.y; acc0.z += a.x*b.z; acc0.w += a.x*b.w;
            acc1.x += a.y*b.x; acc1.y += a.y*b.y; acc1.z += a.y*b.z; acc1.w += a.y*b.w;
            acc2.x += a.z*b.x; acc2.y += a.z*b.y; acc2.z += a.z*b.z; acc2.w += a.z*b.w;
            acc3.x += a.w*b.x; acc3.y += a.w*b.y; acc3.z += a.w*b.z; acc3.w += a.w*b.w;
        }
        __syncthreads();
    }

    float4 accs[4] = {acc0, acc1, acc2, acc3};
    #pragma unroll
    for (int i = 0; i < 4; ++i) {
        int m = m0 + ty * 4 + i;
        float bv = bias[m];
        float4 c = accs[i];
        c.x += bv; c.y += bv; c.z += bv; c.w += bv;
        if (RELU6) {
            c.x = fminf(fmaxf(c.x, 0.f), 6.f);
            c.y = fminf(fmaxf(c.y, 0.f), 6.f);
            c.z = fminf(fmaxf(c.z, 0.f), 6.f);
            c.w = fminf(fmaxf(c.w, 0.f), 6.f);
        }
        if (ADDRES) {
            float4 r = *(const float4*)&R[zO + (size_t)m * NN + n0 + tx * 4];
            c.x += r.x; c.y += r.y; c.z += r.z; c.w += r.w;
        }
        *(float4*)&out[zO + (size_t)m * NN + n0 + tx * 4] = c;
    }
}

// ---------------------------------------------------------------------------
// Fused attention: per block: one (b, h, 64-row tile).
// Single-pass softmax (no max subtraction; logits are O(10) << 88).
// Shared: Ks[16][132], Vs[64][132], Ss[64][132] = 76032 B dynamic.
// Thread (r = tid>>2, dg = tid&3): owns row r, d = dg + 4*dd (dd<16).
// Bank-group analysis: all LDS.128 in PV loop hit 4 distinct bank groups.
// ---------------------------------------------------------------------------
#define ATT_SMEM_FLOATS (16*132 + 64*132 + 64*132)

__global__ void __launch_bounds__(256) attn_kernel(
    const float* __restrict__ qb, const float* __restrict__ kb,
    const float* __restrict__ vb, float* __restrict__ ob)
{
    extern __shared__ float sm[];
    float* Ks = sm;                 // 16*132
    float* Vs = Ks + 16 * 132;      // 64*132
    float* Ss = Vs + 64 * 132;      // 64*132

    const int tid = threadIdx.x;
    const int r   = tid >> 2;       // 0..63 local row
    const int dg  = tid & 3;        // 0..3
    const int h   = blockIdx.y;
    const int r0  = blockIdx.x * 64;
    const size_t baseQK = (size_t)(blockIdx.z * CDIM + h * KDIM) * NPOS;
    const size_t baseV  = (size_t)(blockIdx.z * DH   + h * DV  ) * NPOS;
    const float* qh = qb + baseQK;
    const float* kh = kb + baseQK;
    const float* vh = vb + baseV;

    // Load q row, fold in the sqrt(kd)=4 scale.
    float ql[16];
    #pragma unroll
    for (int kd = 0; kd < 16; ++kd)
        ql[kd] = qh[kd * NPOS + r0 + r] * 4.0f;

    float f[16];
    #pragma unroll
    for (int dd = 0; dd < 16; ++dd) f[dd] = 0.f;
    float ssum = 0.f;

    for (int t = 0; t < 8; ++t) {
        const int m0 = t * 128;
        __syncthreads();
        for (int idx = tid; idx < 16 * 128; idx += 256) {
            int kd = idx >> 7, mm = idx & 127;
            Ks[kd * 132 + mm] = kh[kd * NPOS + m0 + mm];
        }
        for (int idx = tid; idx < 64 * 128; idx += 256) {
            int d = idx >> 7, mm = idx & 127;
            Vs[d * 132 + mm] = vh[(size_t)d * NPOS + m0 + mm];
        }
        __syncthreads();

        // Scores + exp for this thread's 32 columns (mm4 = i*4 + dg)
        #pragma unroll
        for (int i = 0; i < 8; ++i) {
            int mm4 = i * 4 + dg;
            float4 a = {0.f, 0.f, 0.f, 0.f};
            #pragma unroll
            for (int kd = 0; kd < 16; ++kd) {
                float4 kv = *(const float4*)&Ks[kd * 132 + mm4 * 4];
                a.x += ql[kd] * kv.x; a.y += ql[kd] * kv.y;
                a.z += ql[kd] * kv.z; a.w += ql[kd] * kv.w;
            }
            float4 p;
            p.x = __expf(a.x); p.y = __expf(a.y);
            p.z = __expf(a.z); p.w = __expf(a.w);
            ssum += p.x + p.y + p.z + p.w;
            *(float4*)&Ss[r * 132 + mm4 * 4] = p;
        }
        __syncthreads();

        // P @ V for this thread's 16 d-lanes
        #pragma unroll 4
        for (int mm4 = 0; mm4 < 32; ++mm4) {
            float4 p4 = *(const float4*)&Ss[r * 132 + mm4 * 4];
            #pragma unroll
            for (int dd = 0; dd < 16; ++dd) {
                int d = dg + dd * 4;
                float4 v4 = *(const float4*)&Vs[d * 132 + mm4 * 4];
                f[dd] += p4.x * v4.x + p4.y * v4.y + p4.z * v4.z + p4.w * v4.w;
            }
        }
    }

    // row sum across the 4 lanes owning this row (lanes 4r..4r+3)
    ssum += __shfl_xor_sync(0xffffffffu, ssum, 1);
    ssum += __shfl_xor_sync(0xffffffffu, ssum, 2);
    float inv = 1.0f / ssum;

    #pragma unroll
    for (int dd = 0; dd < 16; ++dd) {
        int d = dg + dd * 4;
        ob[baseV + (size_t)d * NPOS + r0 + r] = f[dd] * inv;
    }
}

// ---------------------------------------------------------------------------
// Launch
// ---------------------------------------------------------------------------
extern "C" void kernel_launch(void* const* d_in, const int* in_sizes, int n_in,
                              void* d_out, int out_size)
{
    (void)in_sizes; (void)n_in; (void)out_size;
    const float* x   = (const float*)d_in[0];
    const float* g1  = (const float*)d_in[1];
    const float* b1  = (const float*)d_in[2];
    const float* wq  = (const float*)d_in[3];
    const float* bq  = (const float*)d_in[4];
    const float* wk  = (const float*)d_in[5];
    const float* bk  = (const float*)d_in[6];
    const float* wv  = (const float*)d_in[7];
    const float* bv  = (const float*)d_in[8];
    const float* wp  = (const float*)d_in[9];
    const float* bp  = (const float*)d_in[10];
    const float* g2  = (const float*)d_in[11];
    const float* b2  = (const float*)d_in[12];
    const float* w1  = (const float*)d_in[13];
    const float* bb1 = (const float*)d_in[14];
    const float* w2  = (const float*)d_in[15];
    const float* bb2 = (const float*)d_in[16];
    float* out = (float*)d_out;

    float* base = nullptr;
    cudaGetSymbolAddress((void**)&base, g_buf);
    float* Yb  = base + OFF_Y;
    float* Qb  = base + OFF_Q;
    float* Kb  = base + OFF_K;
    float* Vb  = base + OFF_V;
    float* Ob  = base + OFF_O;
    float* X2b = base + OFF_X2;
    float* Y2b = base + OFF_Y2;
    float* Hb  = base + OFF_H;

    cudaFuncSetAttribute(attn_kernel, cudaFuncAttributeMaxDynamicSharedMemorySize,
                         ATT_SMEM_FLOATS * (int)sizeof(float));

    // 1) BN1
    bn_kernel<<<CDIM, 256>>>(x, Yb, g1, b1);

    // 2) Q, K, V projections
    gemm_kernel<0,0><<<dim3(NPOS/64, CDIM/64, BATCH), 256>>>(wq, Yb, bq, nullptr, Qb, CDIM, CDIM, NPOS);
    gemm_kernel<0,0><<<dim3(NPOS/64, CDIM/64, BATCH), 256>>>(wk, Yb, bk, nullptr, Kb, CDIM, CDIM, NPOS);
    gemm_kernel<0,0><<<dim3(NPOS/64, DH/64,   BATCH), 256>>>(wv, Yb, bv, nullptr, Vb, DH,   CDIM, NPOS);

    // 3) Attention
    attn_kernel<<<dim3(NPOS/64, NH, BATCH), 256, ATT_SMEM_FLOATS * sizeof(float)>>>(Qb, Kb, Vb, Ob);

    // 4) Projection + residual (res = x)
    gemm_kernel<0,1><<<dim3(NPOS/64, CDIM/64, BATCH), 256>>>(wp, Ob, bp, x, X2b, CDIM, DH, NPOS);

    // 5) BN2
    bn_kernel<<<CDIM, 256>>>(X2b, Y2b, g2, b2);

    // 6) MLP: relu6(w1 @ y2 + bb1), then w2 @ h + bb2 + residual -> out
    gemm_kernel<1,0><<<dim3(NPOS/64, HID/64,  BATCH), 256>>>(w1, Y2b, bb1, nullptr, Hb, HID, CDIM, NPOS);
    gemm_kernel<0,1><<<dim3(NPOS/64, CDIM/64, BATCH), 256>>>(w2, Hb, bb2, X2b, out, CDIM, HID, NPOS);
}